// round 11
// baseline (speedup 1.0000x reference)
#include <cuda_runtime.h>
#include <cuda_bf16.h>

// RNN: out[n,t,:] = tanh(x[n,t,:]@Wx + b + h_{t-1}@Wh), h_{-1}=h0.
// N=64, T=512, D=256, H=256, all fp32.
//
// SINGLE fused kernel. 64 clusters x 2 CTAs x 256 threads. CTA r owns output
// columns [r*128,+128).
//   Warps 0-3 (A): per step, dot the LOCAL k-half -> p_s, then compute a
//     1/16 slice of a future xw tile (x@Wx+b) into a 3-deep smem ring, plus
//     X-tile staging and Wx register prefetch. A never touches the mbarrier.
//   Warps 4-7 (B): read p_s + ring xw BEFORE the arrival wait, wait for the
//     peer h half, dot it, combine + tanh, write local half, send 4x128B
//     per-warp cp.async.bulk chunks with mbarrier::complete_tx (R10 path).
// Ring handoff needs no new sync: tile m is finished 17+ steps before B
// reads it, ordered by the per-step bar2/bar3 chain; if A ever lags, bar3
// self-paces the step.

#define ULL unsigned long long

static __device__ __forceinline__ ULL pk2(float lo, float hi) {
    ULL r; asm("mov.b64 %0, {%1,%2};" : "=l"(r) : "f"(lo), "f"(hi)); return r;
}
static __device__ __forceinline__ void upk2(ULL v, float& lo, float& hi) {
    asm("mov.b64 {%0,%1}, %2;" : "=f"(lo), "=f"(hi) : "l"(v));
}
static __device__ __forceinline__ ULL f2fma(ULL a, ULL b, ULL c) {
    ULL d; asm("fma.rn.f32x2 %0, %1, %2, %3;" : "=l"(d) : "l"(a), "l"(b), "l"(c)); return d;
}
static __device__ __forceinline__ ULL f2add(ULL a, ULL b) {
    ULL d; asm("add.rn.f32x2 %0, %1, %2;" : "=l"(d) : "l"(a), "l"(b)); return d;
}
static __device__ __forceinline__ unsigned int smem_u32(const void* p) {
    unsigned int a;
    asm("{ .reg .u64 t; cvta.to.shared.u64 t, %1; cvt.u32.u64 %0, t; }"
        : "=r"(a) : "l"(p));
    return a;
}
static __device__ __forceinline__ float fast_tanh(float x) {
    float e = __expf(x + x);
    return 1.0f - __fdividef(2.0f, e + 1.0f);
}
static __device__ __forceinline__ void wait_parity(unsigned int bar, unsigned int par) {
    unsigned int done;
    asm volatile(
        "{ .reg .pred p; "
        "mbarrier.try_wait.parity.acquire.cta.shared::cta.b64 p, [%1], %2; "
        "selp.b32 %0, 1, 0, p; }"
        : "=r"(done) : "r"(bar), "r"(par) : "memory");
    while (!done) {
        asm volatile(
            "{ .reg .pred p; "
            "mbarrier.try_wait.parity.acquire.cta.shared::cta.b64 p, [%1], %2, 0x989680; "
            "selp.b32 %0, 1, 0, p; }"
            : "=r"(done) : "r"(bar), "r"(par) : "memory");
    }
}
// 128-element dot: 32x LDS.128 (broadcast), 64 FFMA2 over 8 chains.
static __device__ __forceinline__ float dot128(const ulonglong2* hp, const ULL* W2) {
    ULL a0 = 0ULL, a1 = 0ULL, a2 = 0ULL, a3 = 0ULL;
    ULL a4 = 0ULL, a5 = 0ULL, a6 = 0ULL, a7 = 0ULL;
#pragma unroll
    for (int q = 0; q < 32; q += 4) {
        ulonglong2 v0 = hp[q],     v1 = hp[q + 1];
        ulonglong2 v2 = hp[q + 2], v3 = hp[q + 3];
        a0 = f2fma(v0.x, W2[2 * q],     a0);
        a1 = f2fma(v0.y, W2[2 * q + 1], a1);
        a2 = f2fma(v1.x, W2[2 * q + 2], a2);
        a3 = f2fma(v1.y, W2[2 * q + 3], a3);
        a4 = f2fma(v2.x, W2[2 * q + 4], a4);
        a5 = f2fma(v2.y, W2[2 * q + 5], a5);
        a6 = f2fma(v3.x, W2[2 * q + 6], a6);
        a7 = f2fma(v3.y, W2[2 * q + 7], a7);
    }
    ULL ss = f2add(f2add(f2add(a0, a1), f2add(a2, a3)),
                   f2add(f2add(a4, a5), f2add(a6, a7)));
    float lo, hi;
    upk2(ss, lo, hi);
    return lo + hi;
}
// One k-slice (16 k's) of the xw tile: acc2[i] += X[i][k0..+16] . Wx-pairs.
// Xs row = 256 floats; all A threads read the same addresses (broadcast).
static __device__ __forceinline__ void gemm_slice(const float* Xs_tile,
                                                  const ULL* wxp, ULL* acc2,
                                                  int k0) {
#pragma unroll
    for (int i = 0; i < 16; i++) {
        const ulonglong2* xp = (const ulonglong2*)(Xs_tile + i * 256 + k0);
        ulonglong2 q0 = xp[0], q1 = xp[1];
        acc2[i] = f2fma(q0.x, wxp[0], acc2[i]);
        acc2[i] = f2fma(q0.y, wxp[1], acc2[i]);
        acc2[i] = f2fma(q1.x, wxp[2], acc2[i]);
        acc2[i] = f2fma(q1.y, wxp[3], acc2[i]);
        ulonglong2 q2 = xp[2], q3 = xp[3];
        acc2[i] = f2fma(q2.x, wxp[4], acc2[i]);
        acc2[i] = f2fma(q2.y, wxp[5], acc2[i]);
        acc2[i] = f2fma(q3.x, wxp[6], acc2[i]);
        acc2[i] = f2fma(q3.y, wxp[7], acc2[i]);
    }
}

__global__ void __launch_bounds__(256, 1) __cluster_dims__(2, 1, 1)
rnn_fused(const float* __restrict__ x, const float* __restrict__ h0g,
          const float* __restrict__ Wx, const float* __restrict__ Wh,
          const float* __restrict__ bias, float* __restrict__ out) {
    extern __shared__ __align__(16) char smem[];
    // Carve dynamic smem.
    ULL*   mbar = (ULL*)smem;                          // 8 B (+pad to 16)
    float* hloc = (float*)(smem + 16);                 // [2][128]
    float* hrem = hloc + 256;                          // [2][128]
    float* p_s  = hrem + 256;                          // [2][128]
    float* ring = p_s + 256;                           // [3][16][128] = 6144 f
    float* Xs   = ring + 6144;                         // [2][16][256] = 8192 f

    const int t     = threadIdx.x;
    const int n     = blockIdx.x >> 1;
    const int r     = blockIdx.x & 1;
    const int jbase = r * 128;
    const int j     = t & 127;
    const int g     = t >> 7;              // 0 = group A, 1 = group B
    const int kbase = (g == 0) ? jbase : (jbase ^ 128);

    // Register-resident Wh slice: Wh[kbase+k][jbase+j], k-pairs.
    ULL W2[64];
#pragma unroll
    for (int k2 = 0; k2 < 64; k2++) {
        float w0 = Wh[(size_t)(kbase + 2 * k2) * 256 + jbase + j];
        float w1 = Wh[(size_t)(kbase + 2 * k2 + 1) * 256 + jbase + j];
        W2[k2] = pk2(w0, w1);
    }

    if (g == 0) hloc[j] = h0g[(size_t)n * 256 + jbase + j];
    else        hrem[j] = h0g[(size_t)n * 256 + (jbase ^ 128) + j];

    const unsigned int bar_local = smem_u32(mbar);
    if (t == 0) {
        asm volatile("mbarrier.init.shared.b64 [%0], %1;"
                     :: "r"(bar_local), "r"(1) : "memory");
    }
    asm volatile("barrier.cluster.arrive.aligned;" ::: "memory");
    asm volatile("barrier.cluster.wait.aligned;" ::: "memory");

    const unsigned int peer = r ^ 1;
    unsigned int rem_dst[2], rem_bar;
    {
        unsigned int l0 = smem_u32(&hrem[0]);
        unsigned int l1 = smem_u32(&hrem[128]);
        asm("mapa.shared::cluster.u32 %0, %1, %2;" : "=r"(rem_dst[0]) : "r"(l0), "r"(peer));
        asm("mapa.shared::cluster.u32 %0, %1, %2;" : "=r"(rem_dst[1]) : "r"(l1), "r"(peer));
        asm("mapa.shared::cluster.u32 %0, %1, %2;" : "=r"(rem_bar) : "r"(bar_local), "r"(peer));
    }
    const unsigned int src_loc[2] = { smem_u32(&hloc[0]), smem_u32(&hloc[128]) };

    if (g == 0) {
        // ================= Group A: local dotter + xw producer =============
        const float* Xg = x + (size_t)n * 512 * 256;   // [512][256]
        const int jj = jbase + j;
        const float bj = bias[jj];
        ULL acc2[16];
#pragma unroll
        for (int i = 0; i < 16; i++) acc2[i] = 0ULL;
        float wl[8], wh[8];

        // ---- Prologue: tiles 0,1 -> ring[0],ring[1]; X2 staged in Xs[0] ----
        for (int f = j; f < 1024; f += 128) {          // X tile 0 -> Xs[0]
            float4 v = *(const float4*)(Xg + 4 * f);
            *(float4*)(Xs + 4 * f) = v;
        }
        for (int f = j; f < 1024; f += 128) {          // X tile 1 -> Xs[1]
            float4 v = *(const float4*)(Xg + 16 * 256 + 4 * f);
            *(float4*)(Xs + 4096 + 4 * f) = v;
        }
        asm volatile("bar.sync 4, 128;" ::: "memory");
        for (int tile = 0; tile < 2; tile++) {
#pragma unroll
            for (int m = 0; m < 8; m++) {              // k-range 0 loads
                wl[m] = Wx[(size_t)(2 * m) * 256 + jj];
                wh[m] = Wx[(size_t)(2 * m + 1) * 256 + jj];
            }
            for (int ks = 0; ks < 16; ks++) {
                ULL wxp[8];
#pragma unroll
                for (int m = 0; m < 8; m++) wxp[m] = pk2(wl[m], wh[m]);
                if (ks < 15) {
                    int kn = 16 * (ks + 1);
#pragma unroll
                    for (int m = 0; m < 8; m++) {
                        wl[m] = Wx[(size_t)(kn + 2 * m) * 256 + jj];
                        wh[m] = Wx[(size_t)(kn + 2 * m + 1) * 256 + jj];
                    }
                }
                gemm_slice(Xs + tile * 4096, wxp, acc2, 16 * ks);
            }
#pragma unroll
            for (int i = 0; i < 16; i++) {
                float lo, hi; upk2(acc2[i], lo, hi);
                ring[tile * 2048 + i * 128 + j] = lo + hi + bj;
                acc2[i] = 0ULL;
            }
        }
        for (int f = j; f < 1024; f += 128) {          // X tile 2 -> Xs[0]
            float4 v = *(const float4*)(Xg + 32 * 256 + 4 * f);
            *(float4*)(Xs + 4 * f) = v;
        }
#pragma unroll
        for (int m = 0; m < 8; m++) {                  // Wx prefetch, k0=0
            wl[m] = Wx[(size_t)(2 * m) * 256 + jj];
            wh[m] = Wx[(size_t)(2 * m + 1) * 256 + jj];
        }
        asm volatile("bar.sync 4, 128;" ::: "memory");

        // ---- Steady loop ----
        float4 xold = make_float4(0.f, 0.f, 0.f, 0.f);
        for (int s = 0; s < 512; s++) {
            const int cur = s & 1;
            if (s > 0) asm volatile("bar.sync 3, 256;" ::: "memory");

            float part = dot128((const ulonglong2*)&hloc[cur * 128], W2);
            p_s[cur * 128 + j] = part;
            asm volatile("bar.arrive 2, 256;" ::: "memory");

            const int ls = s & 15;
            const int w  = s >> 4;
            if (w + 2 <= 31) {                         // produce tile w+2
                ULL wxp[8];
#pragma unroll
                for (int m = 0; m < 8; m++) wxp[m] = pk2(wl[m], wh[m]);
                gemm_slice(Xs + (w & 1) * 4096, wxp, acc2, 16 * ls);
                if (ls == 15) {
                    const int slot = (w + 2) % 3;
#pragma unroll
                    for (int i = 0; i < 16; i++) {
                        float lo, hi; upk2(acc2[i], lo, hi);
                        ring[slot * 2048 + i * 128 + j] = lo + hi + bj;
                        acc2[i] = 0ULL;
                    }
                }
            }
            if (w <= 28) {                             // stage X tile w+3
                float4 xnew = xold;
                if (ls < 8) {
                    int f = ls * 128 + j;
                    xnew = *(const float4*)(Xg + (size_t)(16 * (w + 3)) * 256 + 4 * f);
                }
                if (ls >= 1 && ls <= 8) {
                    int f = (ls - 1) * 128 + j;
                    *(float4*)(Xs + ((w + 1) & 1) * 4096 + 4 * f) = xold;
                }
                xold = xnew;
            }
            if (s + 1 < 480) {                         // Wx prefetch, next k0
                int kn = 16 * ((s + 1) & 15);
#pragma unroll
                for (int m = 0; m < 8; m++) {
                    wl[m] = Wx[(size_t)(kn + 2 * m) * 256 + jj];
                    wh[m] = Wx[(size_t)(kn + 2 * m + 1) * 256 + jj];
                }
            }
            if (ls == 15) asm volatile("bar.sync 4, 128;" ::: "memory");
        }
    } else {
        // ============ Group B: remote dotter + combiner + sender ===========
        const int wchunk = (t - 128) >> 5;
        const unsigned int coff = wchunk * 128;
        for (int s = 0; s < 512; s++) {
            const int cur = s & 1;
            const int nxt = cur ^ 1;

            // A's p_s + ring xw ready well before peer data: read pre-wait.
            asm volatile("bar.sync 2, 256;" ::: "memory");
            float psv = p_s[cur * 128 + j];
            float xwv = ring[((s >> 4) % 3) * 2048 + (s & 15) * 128 + j];

            if (s > 0) wait_parity(bar_local, (unsigned)((s & 1) ^ 1));

            float part = dot128((const ulonglong2*)&hrem[cur * 128], W2);

            float pre = xwv + part + psv;
            float hn  = fast_tanh(pre);
            hloc[nxt * 128 + j] = hn;

            if (s < 511) {
                asm volatile("bar.arrive 3, 256;" ::: "memory");
                __syncwarp();
                asm volatile("fence.proxy.async.shared::cta;" ::: "memory");
                if ((t & 31) == 0) {
                    if (wchunk == 0) {
                        asm volatile("mbarrier.arrive.expect_tx.shared::cta.b64 _, [%0], %1;"
                                     :: "r"(bar_local), "r"(512) : "memory");
                    }
                    asm volatile(
                        "cp.async.bulk.shared::cluster.shared::cta.mbarrier::complete_tx::bytes "
                        "[%0], [%1], %2, [%3];"
                        :: "r"(rem_dst[nxt] + coff), "r"(src_loc[nxt] + coff),
                           "r"(128), "r"(rem_bar)
                        : "memory");
                }
            }
            out[((size_t)n * 512 + s) * 256 + jbase + j] = hn;
        }
    }

    // Don't exit while the peer may still write into our SMEM.
    asm volatile("barrier.cluster.arrive.aligned;" ::: "memory");
    asm volatile("barrier.cluster.wait.aligned;" ::: "memory");
}

// ---------------------------------------------------------------------------
extern "C" void kernel_launch(void* const* d_in, const int* in_sizes, int n_in,
                              void* d_out, int out_size) {
    const float* x  = (const float*)d_in[0];  // (64,512,256)
    const float* h0 = (const float*)d_in[1];  // (64,256)
    const float* Wx = (const float*)d_in[2];  // (256,256)
    const float* Wh = (const float*)d_in[3];  // (256,256)
    const float* b  = (const float*)d_in[4];  // (256,)
    float* out = (float*)d_out;               // (64,512,256)

    // smem: 16 (mbar) + 3*256*4 (h/p) + 6144*4 (ring) + 8192*4 (Xs) = 60,432 B
    const int smem_bytes = 16 + 3 * 256 * 4 + 6144 * 4 + 8192 * 4;
    cudaFuncSetAttribute(rnn_fused, cudaFuncAttributeMaxDynamicSharedMemorySize,
                         smem_bytes);
    rnn_fused<<<128, 256, smem_bytes>>>(x, h0, Wx, Wh, b, out);
    (void)in_sizes; (void)n_in; (void)out_size;
}

// round 13
// speedup vs baseline: 1.5802x; 1.5802x over previous
#include <cuda_runtime.h>
#include <cuda_bf16.h>

// RNN: out[n,t,:] = tanh(x[n,t,:]@Wx + b + h_{t-1}@Wh), h_{-1}=h0.
// N=64, T=512, D=256, H=256, all fp32.
//
// Kernel 1: xW = x@Wx + b -> g_xw (SIMT f32x2 GEMM).
// Kernel 2: recurrence, 64 clusters x 2 CTAs, 256 threads (R10 structure,
//   proven). Warps 0-3 (A) dot the LOCAL k-half -> p_s. Warps 4-7 (B) read
//   p_s BEFORE the arrival wait, wait for the peer half, dot it, combine +
//   tanh.approx (single MUFU), write local half, send 4x128B per-warp
//   cp.async.bulk chunks with mbarrier::complete_tx.

#define ULL unsigned long long

static __device__ __forceinline__ ULL pk2(float lo, float hi) {
    ULL r; asm("mov.b64 %0, {%1,%2};" : "=l"(r) : "f"(lo), "f"(hi)); return r;
}
static __device__ __forceinline__ void upk2(ULL v, float& lo, float& hi) {
    asm("mov.b64 {%0,%1}, %2;" : "=f"(lo), "=f"(hi) : "l"(v));
}
static __device__ __forceinline__ ULL f2fma(ULL a, ULL b, ULL c) {
    ULL d; asm("fma.rn.f32x2 %0, %1, %2, %3;" : "=l"(d) : "l"(a), "l"(b), "l"(c)); return d;
}
static __device__ __forceinline__ ULL f2add(ULL a, ULL b) {
    ULL d; asm("add.rn.f32x2 %0, %1, %2;" : "=l"(d) : "l"(a), "l"(b)); return d;
}
static __device__ __forceinline__ unsigned int smem_u32(const void* p) {
    unsigned int a;
    asm("{ .reg .u64 t; cvta.to.shared.u64 t, %1; cvt.u32.u64 %0, t; }"
        : "=r"(a) : "l"(p));
    return a;
}
// Single-instruction hardware tanh (MUFU.TANH, sm_75+). ~1e-5 rel accuracy.
static __device__ __forceinline__ float fast_tanh(float x) {
    float y;
    asm("tanh.approx.f32 %0, %1;" : "=f"(y) : "f"(x));
    return y;
}
static __device__ __forceinline__ void wait_parity(unsigned int bar, unsigned int par) {
    unsigned int done;
    asm volatile(
        "{ .reg .pred p; "
        "mbarrier.try_wait.parity.acquire.cta.shared::cta.b64 p, [%1], %2; "
        "selp.b32 %0, 1, 0, p; }"
        : "=r"(done) : "r"(bar), "r"(par) : "memory");
    while (!done) {
        asm volatile(
            "{ .reg .pred p; "
            "mbarrier.try_wait.parity.acquire.cta.shared::cta.b64 p, [%1], %2, 0x989680; "
            "selp.b32 %0, 1, 0, p; }"
            : "=r"(done) : "r"(bar), "r"(par) : "memory");
    }
}
// 128-element dot: 32x LDS.128 (broadcast), 64 FFMA2 over 8 chains.
static __device__ __forceinline__ float dot128(const ulonglong2* hp, const ULL* W2) {
    ULL a0 = 0ULL, a1 = 0ULL, a2 = 0ULL, a3 = 0ULL;
    ULL a4 = 0ULL, a5 = 0ULL, a6 = 0ULL, a7 = 0ULL;
#pragma unroll
    for (int q = 0; q < 32; q += 4) {
        ulonglong2 v0 = hp[q],     v1 = hp[q + 1];
        ulonglong2 v2 = hp[q + 2], v3 = hp[q + 3];
        a0 = f2fma(v0.x, W2[2 * q],     a0);
        a1 = f2fma(v0.y, W2[2 * q + 1], a1);
        a2 = f2fma(v1.x, W2[2 * q + 2], a2);
        a3 = f2fma(v1.y, W2[2 * q + 3], a3);
        a4 = f2fma(v2.x, W2[2 * q + 4], a4);
        a5 = f2fma(v2.y, W2[2 * q + 5], a5);
        a6 = f2fma(v3.x, W2[2 * q + 6], a6);
        a7 = f2fma(v3.y, W2[2 * q + 7], a7);
    }
    ULL ss = f2add(f2add(f2add(a0, a1), f2add(a2, a3)),
                   f2add(f2add(a4, a5), f2add(a6, a7)));
    float lo, hi;
    upk2(ss, lo, hi);
    return lo + hi;
}

// Scratch for the input projection (no cudaMalloc allowed).
__device__ float g_xw[64 * 512 * 256];

// ---------------------------------------------------------------------------
// Kernel 1: xW GEMM.  C[M=32768, H=256] = X[M,256] * Wx[256,256] + b
// ---------------------------------------------------------------------------
__global__ void __launch_bounds__(256) gemm_xw(const float* __restrict__ X,
                                               const float* __restrict__ Wx,
                                               const float* __restrict__ bias) {
    __shared__ __align__(16) float As[16][128];  // [k][m]
    __shared__ __align__(16) float Bs[16][128];  // [k][h]

    const int t    = threadIdx.x;
    const int m0   = blockIdx.x * 128;
    const int h0   = blockIdx.y * 128;
    const int warp = t >> 5;
    const int lane = t & 31;

    ULL acc[8][4];
#pragma unroll
    for (int p = 0; p < 8; p++)
#pragma unroll
        for (int c = 0; c < 4; c++) acc[p][c] = 0ULL;

    for (int k0 = 0; k0 < 256; k0 += 16) {
#pragma unroll
        for (int i = 0; i < 2; i++) {
            int s   = t * 2 + i;
            int row = s >> 2;
            int kq  = s & 3;
            float4 v = *(const float4*)&X[(size_t)(m0 + row) * 256 + k0 + kq * 4];
            As[kq * 4 + 0][row] = v.x;
            As[kq * 4 + 1][row] = v.y;
            As[kq * 4 + 2][row] = v.z;
            As[kq * 4 + 3][row] = v.w;
        }
#pragma unroll
        for (int i = 0; i < 2; i++) {
            int s  = t * 2 + i;
            int kr = s >> 5;
            int hq = s & 31;
            float4 v = *(const float4*)&Wx[(size_t)(k0 + kr) * 256 + h0 + hq * 4];
            *(float4*)&Bs[kr][hq * 4] = v;
        }
        __syncthreads();

#pragma unroll
        for (int kk = 0; kk < 16; kk++) {
            const ulonglong2* ar = (const ulonglong2*)&As[kk][warp * 16];
            ulonglong2 q0 = ar[0], q1 = ar[1], q2 = ar[2], q3 = ar[3];
            ULL ap[8] = {q0.x, q0.y, q1.x, q1.y, q2.x, q2.y, q3.x, q3.y};
            float4 bv = *(const float4*)&Bs[kk][lane * 4];
            ULL bs0 = pk2(bv.x, bv.x), bs1 = pk2(bv.y, bv.y);
            ULL bs2 = pk2(bv.z, bv.z), bs3 = pk2(bv.w, bv.w);
#pragma unroll
            for (int p = 0; p < 8; p++) {
                acc[p][0] = f2fma(ap[p], bs0, acc[p][0]);
                acc[p][1] = f2fma(ap[p], bs1, acc[p][1]);
                acc[p][2] = f2fma(ap[p], bs2, acc[p][2]);
                acc[p][3] = f2fma(ap[p], bs3, acc[p][3]);
            }
        }
        __syncthreads();
    }

    float4 bb = *(const float4*)&bias[h0 + lane * 4];
#pragma unroll
    for (int p = 0; p < 8; p++) {
        float lo0, hi0, lo1, hi1, lo2, hi2, lo3, hi3;
        upk2(acc[p][0], lo0, hi0);
        upk2(acc[p][1], lo1, hi1);
        upk2(acc[p][2], lo2, hi2);
        upk2(acc[p][3], lo3, hi3);
        int m = m0 + warp * 16 + p * 2;
        float4 r0 = make_float4(lo0 + bb.x, lo1 + bb.y, lo2 + bb.z, lo3 + bb.w);
        float4 r1 = make_float4(hi0 + bb.x, hi1 + bb.y, hi2 + bb.z, hi3 + bb.w);
        *(float4*)&g_xw[(size_t)m * 256 + h0 + lane * 4]       = r0;
        *(float4*)&g_xw[(size_t)(m + 1) * 256 + h0 + lane * 4] = r1;
    }
}

// ---------------------------------------------------------------------------
// Kernel 2: recurrence. grid = 128 blocks x 256 thr, cluster (2,1,1).
// ---------------------------------------------------------------------------
__global__ void __launch_bounds__(256, 1) __cluster_dims__(2, 1, 1)
rnn_scan(const float* __restrict__ h0g, const float* __restrict__ Wh,
         float* __restrict__ out) {
    __shared__ __align__(16) float hloc[2][128];   // our columns of h
    __shared__ __align__(16) float hrem[2][128];   // peer's columns (bulk-filled)
    __shared__ float p_s[2][128];                  // group A partials
    __shared__ __align__(8) ULL mbar;

    const int t     = threadIdx.x;
    const int n     = blockIdx.x >> 1;
    const int r     = blockIdx.x & 1;
    const int jbase = r * 128;
    const int j     = t & 127;
    const int g     = t >> 7;              // 0 = group A (local), 1 = group B
    const int kbase = (g == 0) ? jbase : (jbase ^ 128);

    // Register-resident weight slice: Wh[kbase+k][jbase+j], k-pairs.
    ULL W2[64];
#pragma unroll
    for (int k2 = 0; k2 < 64; k2++) {
        float w0 = Wh[(size_t)(kbase + 2 * k2) * 256 + jbase + j];
        float w1 = Wh[(size_t)(kbase + 2 * k2 + 1) * 256 + jbase + j];
        W2[k2] = pk2(w0, w1);
    }

    if (g == 0) hloc[0][j] = h0g[(size_t)n * 256 + jbase + j];
    else        hrem[0][j] = h0g[(size_t)n * 256 + (jbase ^ 128) + j];

    const unsigned int bar_local = smem_u32(&mbar);
    if (t == 0) {
        asm volatile("mbarrier.init.shared.b64 [%0], %1;"
                     :: "r"(bar_local), "r"(1) : "memory");
    }
    // Cluster-wide barrier: init writes visible everywhere before traffic.
    asm volatile("barrier.cluster.arrive.aligned;" ::: "memory");
    asm volatile("barrier.cluster.wait.aligned;" ::: "memory");

    const unsigned int peer = r ^ 1;
    unsigned int rem_dst[2], rem_bar;
    {
        unsigned int l0 = smem_u32(&hrem[0][0]);
        unsigned int l1 = smem_u32(&hrem[1][0]);
        asm("mapa.shared::cluster.u32 %0, %1, %2;" : "=r"(rem_dst[0]) : "r"(l0), "r"(peer));
        asm("mapa.shared::cluster.u32 %0, %1, %2;" : "=r"(rem_dst[1]) : "r"(l1), "r"(peer));
        asm("mapa.shared::cluster.u32 %0, %1, %2;" : "=r"(rem_bar) : "r"(bar_local), "r"(peer));
    }
    const unsigned int src_loc[2] = { smem_u32(&hloc[0][0]), smem_u32(&hloc[1][0]) };

    const float* xwp = g_xw + (size_t)n * 512 * 256 + jbase;

    if (g == 0) {
        // ----- Group A: local-half dotter, never waits on the mbarrier -----
        for (int s = 0; s < 512; s++) {
            const int cur = s & 1;
            if (s > 0) {
                // Wait for B's hloc[cur] writes from step s-1.
                asm volatile("bar.sync 3, 256;" ::: "memory");
            }
            float part = dot128((const ulonglong2*)&hloc[cur][0], W2);
            p_s[cur][j] = part;
            asm volatile("bar.arrive 2, 256;" ::: "memory");
        }
    } else {
        // ----- Group B: remote-half dotter + combiner + sender -----
        const int wchunk = (t - 128) >> 5;          // B warp index 0..3
        const unsigned int coff = wchunk * 128;     // 32 floats per warp chunk
        float xw_cur = xwp[j];
        for (int s = 0; s < 512; s++) {
            const int cur = s & 1;
            const int nxt = cur ^ 1;

            // Prefetch next step's input projection.
            int sn = (s + 1 < 512) ? (s + 1) : s;
            float xw_nxt = xwp[(size_t)sn * 256 + j];

            // A's p_s[cur] is ready well before the peer data arrives: take
            // the barrier + LDS off the post-arrival critical path.
            asm volatile("bar.sync 2, 256;" ::: "memory");
            float base = xw_cur + p_s[cur][j];

            // Wait for the peer's half of h[cur] (step s-1's send).
            if (s > 0) wait_parity(bar_local, (unsigned)((s & 1) ^ 1));

            float part = dot128((const ulonglong2*)&hrem[cur][0], W2);

            float hn = fast_tanh(base + part);
            hloc[nxt][j] = hn;
            xw_cur = xw_nxt;

            if (s < 511) {
                // Release A for step s+1 (non-blocking).
                asm volatile("bar.arrive 3, 256;" ::: "memory");
                // Per-warp chunked send: this warp's 32 floats are written.
                __syncwarp();
                asm volatile("fence.proxy.async.shared::cta;" ::: "memory");
                if ((t & 31) == 0) {
                    if (wchunk == 0) {
                        // Arm our own barrier for the peer's incoming 512B.
                        asm volatile("mbarrier.arrive.expect_tx.shared::cta.b64 _, [%0], %1;"
                                     :: "r"(bar_local), "r"(512) : "memory");
                    }
                    asm volatile(
                        "cp.async.bulk.shared::cluster.shared::cta.mbarrier::complete_tx::bytes "
                        "[%0], [%1], %2, [%3];"
                        :: "r"(rem_dst[nxt] + coff), "r"(src_loc[nxt] + coff),
                           "r"(128), "r"(rem_bar)
                        : "memory");
                }
            }
            out[((size_t)n * 512 + s) * 256 + jbase + j] = hn;
        }
    }

    // Don't exit while the peer may still write into our SMEM.
    asm volatile("barrier.cluster.arrive.aligned;" ::: "memory");
    asm volatile("barrier.cluster.wait.aligned;" ::: "memory");
}

// ---------------------------------------------------------------------------
extern "C" void kernel_launch(void* const* d_in, const int* in_sizes, int n_in,
                              void* d_out, int out_size) {
    const float* x  = (const float*)d_in[0];  // (64,512,256)
    const float* h0 = (const float*)d_in[1];  // (64,256)
    const float* Wx = (const float*)d_in[2];  // (256,256)
    const float* Wh = (const float*)d_in[3];  // (256,256)
    const float* b  = (const float*)d_in[4];  // (256,)
    float* out = (float*)d_out;               // (64,512,256)

    dim3 g1(256, 2);
    gemm_xw<<<g1, 256>>>(x, Wx, b);
    rnn_scan<<<128, 256>>>(h0, Wh, out);
    (void)in_sizes; (void)n_in; (void)out_size;
}

// round 14
// speedup vs baseline: 1.6494x; 1.0438x over previous
#include <cuda_runtime.h>
#include <cuda_bf16.h>

// RNN: out[n,t,:] = tanh(x[n,t,:]@Wx + b + h_{t-1}@Wh), h_{-1}=h0.
// N=64, T=512, D=256, H=256, all fp32.
//
// Kernel 1: xW = x@Wx + b -> g_xw (SIMT f32x2 GEMM, 64x128 tiles for wave
//   balance: 1024 blocks ~ 6.9 waves).
// Kernel 2: recurrence, 64 clusters x 2 CTAs, 256 threads. Warps 0-3 (A) dot
//   the LOCAL k-half -> p_s. Warps 4-7 (B): prefetch, mbar-wait the peer
//   half, dot it, THEN bar.sync2 + p_s (A's dot ran in parallel under the
//   fabric window), tanh.approx, write local half, send 4x128B per-warp
//   cp.async.bulk chunks with mbarrier::complete_tx.

#define ULL unsigned long long

static __device__ __forceinline__ ULL pk2(float lo, float hi) {
    ULL r; asm("mov.b64 %0, {%1,%2};" : "=l"(r) : "f"(lo), "f"(hi)); return r;
}
static __device__ __forceinline__ void upk2(ULL v, float& lo, float& hi) {
    asm("mov.b64 {%0,%1}, %2;" : "=f"(lo), "=f"(hi) : "l"(v));
}
static __device__ __forceinline__ ULL f2fma(ULL a, ULL b, ULL c) {
    ULL d; asm("fma.rn.f32x2 %0, %1, %2, %3;" : "=l"(d) : "l"(a), "l"(b), "l"(c)); return d;
}
static __device__ __forceinline__ ULL f2add(ULL a, ULL b) {
    ULL d; asm("add.rn.f32x2 %0, %1, %2;" : "=l"(d) : "l"(a), "l"(b)); return d;
}
static __device__ __forceinline__ unsigned int smem_u32(const void* p) {
    unsigned int a;
    asm("{ .reg .u64 t; cvta.to.shared.u64 t, %1; cvt.u32.u64 %0, t; }"
        : "=r"(a) : "l"(p));
    return a;
}
// Single-instruction hardware tanh (MUFU.TANH, sm_75+). ~1e-5 rel accuracy.
static __device__ __forceinline__ float fast_tanh(float x) {
    float y;
    asm("tanh.approx.f32 %0, %1;" : "=f"(y) : "f"(x));
    return y;
}
static __device__ __forceinline__ void wait_parity(unsigned int bar, unsigned int par) {
    unsigned int done;
    asm volatile(
        "{ .reg .pred p; "
        "mbarrier.try_wait.parity.acquire.cta.shared::cta.b64 p, [%1], %2; "
        "selp.b32 %0, 1, 0, p; }"
        : "=r"(done) : "r"(bar), "r"(par) : "memory");
    while (!done) {
        asm volatile(
            "{ .reg .pred p; "
            "mbarrier.try_wait.parity.acquire.cta.shared::cta.b64 p, [%1], %2, 0x989680; "
            "selp.b32 %0, 1, 0, p; }"
            : "=r"(done) : "r"(bar), "r"(par) : "memory");
    }
}
// 128-element dot: 32x LDS.128 (broadcast), 64 FFMA2 over 8 chains.
static __device__ __forceinline__ float dot128(const ulonglong2* hp, const ULL* W2) {
    ULL a0 = 0ULL, a1 = 0ULL, a2 = 0ULL, a3 = 0ULL;
    ULL a4 = 0ULL, a5 = 0ULL, a6 = 0ULL, a7 = 0ULL;
#pragma unroll
    for (int q = 0; q < 32; q += 4) {
        ulonglong2 v0 = hp[q],     v1 = hp[q + 1];
        ulonglong2 v2 = hp[q + 2], v3 = hp[q + 3];
        a0 = f2fma(v0.x, W2[2 * q],     a0);
        a1 = f2fma(v0.y, W2[2 * q + 1], a1);
        a2 = f2fma(v1.x, W2[2 * q + 2], a2);
        a3 = f2fma(v1.y, W2[2 * q + 3], a3);
        a4 = f2fma(v2.x, W2[2 * q + 4], a4);
        a5 = f2fma(v2.y, W2[2 * q + 5], a5);
        a6 = f2fma(v3.x, W2[2 * q + 6], a6);
        a7 = f2fma(v3.y, W2[2 * q + 7], a7);
    }
    ULL ss = f2add(f2add(f2add(a0, a1), f2add(a2, a3)),
                   f2add(f2add(a4, a5), f2add(a6, a7)));
    float lo, hi;
    upk2(ss, lo, hi);
    return lo + hi;
}

// Scratch for the input projection (no cudaMalloc allowed).
__device__ float g_xw[64 * 512 * 256];

// ---------------------------------------------------------------------------
// Kernel 1: xW GEMM.  C[M=32768, H=256] = X[M,256] * Wx[256,256] + b
// Tile 64(M) x 128(H), BK=16, 256 threads; 8 warps x 8 rows, 4 row-pairs.
// ---------------------------------------------------------------------------
__global__ void __launch_bounds__(256) gemm_xw(const float* __restrict__ X,
                                               const float* __restrict__ Wx,
                                               const float* __restrict__ bias) {
    __shared__ __align__(16) float As[16][64];   // [k][m]
    __shared__ __align__(16) float Bs[16][128];  // [k][h]

    const int t    = threadIdx.x;
    const int m0   = blockIdx.x * 64;
    const int h0   = blockIdx.y * 128;
    const int warp = t >> 5;
    const int lane = t & 31;

    ULL acc[4][4];
#pragma unroll
    for (int p = 0; p < 4; p++)
#pragma unroll
        for (int c = 0; c < 4; c++) acc[p][c] = 0ULL;

    for (int k0 = 0; k0 < 256; k0 += 16) {
        // A tile (64 rows x 16 k), transposed store: one float4 per thread.
        {
            int row = t >> 2;              // 0..63
            int kq  = t & 3;
            float4 v = *(const float4*)&X[(size_t)(m0 + row) * 256 + k0 + kq * 4];
            As[kq * 4 + 0][row] = v.x;
            As[kq * 4 + 1][row] = v.y;
            As[kq * 4 + 2][row] = v.z;
            As[kq * 4 + 3][row] = v.w;
        }
        // B tile (16 rows x 128 h): two float4 per thread.
#pragma unroll
        for (int i = 0; i < 2; i++) {
            int s  = t * 2 + i;
            int kr = s >> 5;
            int hq = s & 31;
            float4 v = *(const float4*)&Wx[(size_t)(k0 + kr) * 256 + h0 + hq * 4];
            *(float4*)&Bs[kr][hq * 4] = v;
        }
        __syncthreads();

#pragma unroll
        for (int kk = 0; kk < 16; kk++) {
            const ulonglong2* ar = (const ulonglong2*)&As[kk][warp * 8];
            ulonglong2 q0 = ar[0], q1 = ar[1];
            ULL ap[4] = {q0.x, q0.y, q1.x, q1.y};
            float4 bv = *(const float4*)&Bs[kk][lane * 4];
            ULL bs0 = pk2(bv.x, bv.x), bs1 = pk2(bv.y, bv.y);
            ULL bs2 = pk2(bv.z, bv.z), bs3 = pk2(bv.w, bv.w);
#pragma unroll
            for (int p = 0; p < 4; p++) {
                acc[p][0] = f2fma(ap[p], bs0, acc[p][0]);
                acc[p][1] = f2fma(ap[p], bs1, acc[p][1]);
                acc[p][2] = f2fma(ap[p], bs2, acc[p][2]);
                acc[p][3] = f2fma(ap[p], bs3, acc[p][3]);
            }
        }
        __syncthreads();
    }

    float4 bb = *(const float4*)&bias[h0 + lane * 4];
#pragma unroll
    for (int p = 0; p < 4; p++) {
        float lo0, hi0, lo1, hi1, lo2, hi2, lo3, hi3;
        upk2(acc[p][0], lo0, hi0);
        upk2(acc[p][1], lo1, hi1);
        upk2(acc[p][2], lo2, hi2);
        upk2(acc[p][3], lo3, hi3);
        int m = m0 + warp * 8 + p * 2;
        float4 r0 = make_float4(lo0 + bb.x, lo1 + bb.y, lo2 + bb.z, lo3 + bb.w);
        float4 r1 = make_float4(hi0 + bb.x, hi1 + bb.y, hi2 + bb.z, hi3 + bb.w);
        *(float4*)&g_xw[(size_t)m * 256 + h0 + lane * 4]       = r0;
        *(float4*)&g_xw[(size_t)(m + 1) * 256 + h0 + lane * 4] = r1;
    }
}

// ---------------------------------------------------------------------------
// Kernel 2: recurrence. grid = 128 blocks x 256 thr, cluster (2,1,1).
// ---------------------------------------------------------------------------
__global__ void __launch_bounds__(256, 1) __cluster_dims__(2, 1, 1)
rnn_scan(const float* __restrict__ h0g, const float* __restrict__ Wh,
         float* __restrict__ out) {
    __shared__ __align__(16) float hloc[2][128];   // our columns of h
    __shared__ __align__(16) float hrem[2][128];   // peer's columns (bulk-filled)
    __shared__ float p_s[2][128];                  // group A partials
    __shared__ __align__(8) ULL mbar;

    const int t     = threadIdx.x;
    const int n     = blockIdx.x >> 1;
    const int r     = blockIdx.x & 1;
    const int jbase = r * 128;
    const int j     = t & 127;
    const int g     = t >> 7;              // 0 = group A (local), 1 = group B
    const int kbase = (g == 0) ? jbase : (jbase ^ 128);

    // Register-resident weight slice: Wh[kbase+k][jbase+j], k-pairs.
    ULL W2[64];
#pragma unroll
    for (int k2 = 0; k2 < 64; k2++) {
        float w0 = Wh[(size_t)(kbase + 2 * k2) * 256 + jbase + j];
        float w1 = Wh[(size_t)(kbase + 2 * k2 + 1) * 256 + jbase + j];
        W2[k2] = pk2(w0, w1);
    }

    if (g == 0) hloc[0][j] = h0g[(size_t)n * 256 + jbase + j];
    else        hrem[0][j] = h0g[(size_t)n * 256 + (jbase ^ 128) + j];

    const unsigned int bar_local = smem_u32(&mbar);
    if (t == 0) {
        asm volatile("mbarrier.init.shared.b64 [%0], %1;"
                     :: "r"(bar_local), "r"(1) : "memory");
    }
    // Cluster-wide barrier: init writes visible everywhere before traffic.
    asm volatile("barrier.cluster.arrive.aligned;" ::: "memory");
    asm volatile("barrier.cluster.wait.aligned;" ::: "memory");

    const unsigned int peer = r ^ 1;
    unsigned int rem_dst[2], rem_bar;
    {
        unsigned int l0 = smem_u32(&hrem[0][0]);
        unsigned int l1 = smem_u32(&hrem[1][0]);
        asm("mapa.shared::cluster.u32 %0, %1, %2;" : "=r"(rem_dst[0]) : "r"(l0), "r"(peer));
        asm("mapa.shared::cluster.u32 %0, %1, %2;" : "=r"(rem_dst[1]) : "r"(l1), "r"(peer));
        asm("mapa.shared::cluster.u32 %0, %1, %2;" : "=r"(rem_bar) : "r"(bar_local), "r"(peer));
    }
    const unsigned int src_loc[2] = { smem_u32(&hloc[0][0]), smem_u32(&hloc[1][0]) };

    const float* xwp = g_xw + (size_t)n * 512 * 256 + jbase;

    if (g == 0) {
        // ----- Group A: local-half dotter, never waits on the mbarrier -----
        for (int s = 0; s < 512; s++) {
            const int cur = s & 1;
            if (s > 0) {
                // Wait for B's hloc[cur] writes from step s-1.
                asm volatile("bar.sync 3, 256;" ::: "memory");
            }
            float part = dot128((const ulonglong2*)&hloc[cur][0], W2);
            p_s[cur][j] = part;
            asm volatile("bar.arrive 2, 256;" ::: "memory");
        }
    } else {
        // ----- Group B: remote-half dotter + combiner + sender -----
        const int wchunk = (t - 128) >> 5;          // B warp index 0..3
        const unsigned int coff = wchunk * 128;     // 32 floats per warp chunk
        float xw_cur = xwp[j];
        for (int s = 0; s < 512; s++) {
            const int cur = s & 1;
            const int nxt = cur ^ 1;

            // Prefetch next step's input projection (issue before the wait).
            int sn = (s + 1 < 512) ? (s + 1) : s;
            float xw_nxt = xwp[(size_t)sn * 256 + j];

            // Wait for the peer's half of h[cur] (step s-1's send).
            if (s > 0) wait_parity(bar_local, (unsigned)((s & 1) ^ 1));

            float part = dot128((const ulonglong2*)&hrem[cur][0], W2);

            // A's dot ran in parallel with the fabric window; sync is a
            // fast-path by now, AFTER our own dot.
            asm volatile("bar.sync 2, 256;" ::: "memory");
            float hn = fast_tanh(xw_cur + p_s[cur][j] + part);
            hloc[nxt][j] = hn;
            xw_cur = xw_nxt;

            if (s < 511) {
                // Release A for step s+1 (non-blocking).
                asm volatile("bar.arrive 3, 256;" ::: "memory");
                // Per-warp chunked send: this warp's 32 floats are written.
                __syncwarp();
                asm volatile("fence.proxy.async.shared::cta;" ::: "memory");
                if ((t & 31) == 0) {
                    if (wchunk == 0) {
                        // Arm our own barrier for the peer's incoming 512B.
                        asm volatile("mbarrier.arrive.expect_tx.shared::cta.b64 _, [%0], %1;"
                                     :: "r"(bar_local), "r"(512) : "memory");
                    }
                    asm volatile(
                        "cp.async.bulk.shared::cluster.shared::cta.mbarrier::complete_tx::bytes "
                        "[%0], [%1], %2, [%3];"
                        :: "r"(rem_dst[nxt] + coff), "r"(src_loc[nxt] + coff),
                           "r"(128), "r"(rem_bar)
                        : "memory");
                }
            }
            out[((size_t)n * 512 + s) * 256 + jbase + j] = hn;
        }
    }

    // Don't exit while the peer may still write into our SMEM.
    asm volatile("barrier.cluster.arrive.aligned;" ::: "memory");
    asm volatile("barrier.cluster.wait.aligned;" ::: "memory");
}

// ---------------------------------------------------------------------------
extern "C" void kernel_launch(void* const* d_in, const int* in_sizes, int n_in,
                              void* d_out, int out_size) {
    const float* x  = (const float*)d_in[0];  // (64,512,256)
    const float* h0 = (const float*)d_in[1];  // (64,256)
    const float* Wx = (const float*)d_in[2];  // (256,256)
    const float* Wh = (const float*)d_in[3];  // (256,256)
    const float* b  = (const float*)d_in[4];  // (256,)
    float* out = (float*)d_out;               // (64,512,256)

    dim3 g1(512, 2);   // M/64 x H/128
    gemm_xw<<<g1, 256>>>(x, Wx, b);
    rnn_scan<<<128, 256>>>(h0, Wh, out);
    (void)in_sizes; (void)n_in; (void)out_size;
}